// round 16
// baseline (speedup 1.0000x reference)
#include <cuda_runtime.h>
#include <cuda_fp16.h>

// LightGCN: COO -> fixed-width ELL (W=96), 3 warp-per-row gather SpMM layers.
// Quarter scheme, 8 edges/iter. Per lane-iter: 2 edges multiplied+paired in
// fp16 (HMUL2/HFMA2), flushed to f32 accumulators. Layer 3 fuses the final
// combine out = 0.25*(ego + l1 + l2 + l3).

#define N_USERS 60000
#define N_ITEMS 40000
#define NN      100000
#define NNZ_E   2000000
#define EMB     64
#define NV      (NN * EMB)
#define ELL_W   96                 // multiple of 8; >> max degree (Poisson(20))

// ---- scratch (device globals) ----
__device__ uint4 g_h0[NV / 8];          // ego, fp16
__device__ uint4 g_h1[NV / 8];          // layer-1, fp16
__device__ uint4 g_h2[NV / 8];          // layer-2, fp16
__device__ int   g_count[NN];           // padded counts (multiple of 8)
__device__ int   g_cursor[NN];
__device__ int4  g_edge4[(size_t)NN * ELL_W / 2];   // {col,val} pairs

#define PADC8(c) (((c) + 7) & ~7)

// ---- fp16 helpers ----
__device__ __forceinline__ unsigned h2_as_u(__half2 h) {
    return *reinterpret_cast<unsigned*>(&h);
}
__device__ __forceinline__ __half2 u_as_h2(unsigned u) {
    return *reinterpret_cast<__half2*>(&u);
}
__device__ __forceinline__ uint2 pack_h4(float4 v) {
    return make_uint2(h2_as_u(__floats2half2_rn(v.x, v.y)),
                      h2_as_u(__floats2half2_rn(v.z, v.w)));
}
__device__ __forceinline__ void fma_h4(float4& a, float v, uint2 p) {
    float2 lo = __half22float2(u_as_h2(p.x));
    float2 hi = __half22float2(u_as_h2(p.y));
    a.x = fmaf(v, lo.x, a.x); a.y = fmaf(v, lo.y, a.y);
    a.z = fmaf(v, hi.x, a.z); a.w = fmaf(v, hi.y, a.w);
}

// pair-MAC in fp16: acc += x0*v0 + x1*v1 (8 halves each), flush to f32
__device__ __forceinline__ void mac2_h(float4& alo, float4& ahi,
                                       __half2 v0, __half2 v1,
                                       uint4 x0, uint4 x1) {
    __half2 t0 = __hfma2(v1, u_as_h2(x1.x), __hmul2(v0, u_as_h2(x0.x)));
    __half2 t1 = __hfma2(v1, u_as_h2(x1.y), __hmul2(v0, u_as_h2(x0.y)));
    __half2 t2 = __hfma2(v1, u_as_h2(x1.z), __hmul2(v0, u_as_h2(x0.z)));
    __half2 t3 = __hfma2(v1, u_as_h2(x1.w), __hmul2(v0, u_as_h2(x0.w)));
    float2 f0 = __half22float2(t0); alo.x += f0.x; alo.y += f0.y;
    float2 f1 = __half22float2(t1); alo.z += f1.x; alo.w += f1.y;
    float2 f2 = __half22float2(t2); ahi.x += f2.x; ahi.y += f2.y;
    float2 f3 = __half22float2(t3); ahi.z += f3.x; ahi.w += f3.y;
}

// conv concat(u,it) f32->fp16 into g_h0; fused: init ELL cursors
__global__ void k_conv(const float4* __restrict__ u,
                       const float4* __restrict__ it) {
    int i = blockIdx.x * blockDim.x + threadIdx.x;
    if (i < NN) g_cursor[i] = i * ELL_W;
    const int nU = N_USERS * EMB / 4;
    const int nT = NV / 4;
    if (i >= nT) return;
    float4 v = (i < nU) ? u[i] : it[i - nU];
    ((uint2*)g_h0)[i] = pack_h4(v);
}

// 2 edges per thread: two independent atomic->store chains
__global__ void k_scatter(const float* __restrict__ vals,
                          const int* __restrict__ rows,
                          const int* __restrict__ cols) {
    int e = (blockIdx.x * blockDim.x + threadIdx.x) * 2;
    if (e >= NNZ_E) return;                    // NNZ_E even -> e+1 valid
    int r0 = rows[e],     c0 = cols[e];     float v0 = vals[e];
    int r1 = rows[e + 1], c1 = cols[e + 1]; float v1 = vals[e + 1];
    int p0 = atomicAdd(&g_cursor[r0], 1);
    int p1 = atomicAdd(&g_cursor[r1], 1);
    int2* e2 = (int2*)g_edge4;
    if (p0 < (r0 + 1) * ELL_W) e2[p0] = make_int2(c0, __float_as_int(v0));
    if (p1 < (r1 + 1) * ELL_W) e2[p1] = make_int2(c1, __float_as_int(v1));
}

// derive padded counts + write zero pad slots
__global__ void k_pad() {
    int i = blockIdx.x * blockDim.x + threadIdx.x;
    if (i >= NN) return;
    int s  = i * ELL_W;
    int c  = g_cursor[i] - s;
    if (c > ELL_W) c = ELL_W;
    int pc = PADC8(c);
    g_count[i] = pc;
    int2* e2 = (int2*)g_edge4;
    for (int k = c; k < pc; k++) e2[s + k] = make_int2(0, 0);
}

// One warp per row. q = lane>>3 (quarter), seg = lane&7 owns 16B of the
// 128B fp16 row. 8 edges/iter: 1 int4 metadata LDG per lane (its 2 edges)
// + 2 LDG.128 gathers; fp16 pair-MAC, f32 flush.
template <bool COMB>
__global__ void __launch_bounds__(256) k_spmm(const uint4* __restrict__ x,
                                              uint4* __restrict__ y,
                                              const float4* __restrict__ u,
                                              const float4* __restrict__ it,
                                              float4* __restrict__ out) {
    int w    = (blockIdx.x * blockDim.x + threadIdx.x) >> 5;
    int lane = threadIdx.x & 31;
    if (w >= NN) return;
    int q   = lane >> 3;
    int seg = lane & 7;

    int s = w * ELL_W;
    int n = g_count[w];               // multiple of 8
    float4 alo = make_float4(0.f, 0.f, 0.f, 0.f);
    float4 ahi = make_float4(0.f, 0.f, 0.f, 0.f);

    const int4* ep = g_edge4 + (size_t)(s >> 1);
    for (int j = 0; j < n; j += 8) {
        int4 m = ep[(j >> 1) + q];             // edges s+j+2q, s+j+2q+1
        uint4 xv0 = x[(size_t)m.x * 8 + seg];  // two independent gathers
        uint4 xv1 = x[(size_t)m.z * 8 + seg];
        __half2 v0 = __float2half2_rn(__int_as_float(m.y));
        __half2 v1 = __float2half2_rn(__int_as_float(m.w));
        mac2_h(alo, ahi, v0, v1, xv0, xv1);
    }

    // reduce across the 4 quarters (lane bits 3,4)
    #pragma unroll
    for (int off = 8; off <= 16; off <<= 1) {
        alo.x += __shfl_xor_sync(0xffffffffu, alo.x, off);
        alo.y += __shfl_xor_sync(0xffffffffu, alo.y, off);
        alo.z += __shfl_xor_sync(0xffffffffu, alo.z, off);
        alo.w += __shfl_xor_sync(0xffffffffu, alo.w, off);
        ahi.x += __shfl_xor_sync(0xffffffffu, ahi.x, off);
        ahi.y += __shfl_xor_sync(0xffffffffu, ahi.y, off);
        ahi.z += __shfl_xor_sync(0xffffffffu, ahi.z, off);
        ahi.w += __shfl_xor_sync(0xffffffffu, ahi.w, off);
    }

    if (q == 0) {
        if (!COMB) {
            uint2 plo = pack_h4(alo);
            uint2 phi = pack_h4(ahi);
            y[(size_t)w * 8 + seg] = make_uint4(plo.x, plo.y, phi.x, phi.y);
        } else {
            const float4* ego = (w < N_USERS)
                ? (u  + (size_t)w * 16)
                : (it + (size_t)(w - N_USERS) * 16);
            float4 e0 = ego[seg * 2];
            float4 e1 = ego[seg * 2 + 1];
            uint4 p1 = g_h1[(size_t)w * 8 + seg];
            uint4 p2 = g_h2[(size_t)w * 8 + seg];
            float4 r0 = alo, r1 = ahi;
            fma_h4(r0, 1.f, make_uint2(p1.x, p1.y));
            fma_h4(r1, 1.f, make_uint2(p1.z, p1.w));
            fma_h4(r0, 1.f, make_uint2(p2.x, p2.y));
            fma_h4(r1, 1.f, make_uint2(p2.z, p2.w));
            r0.x = 0.25f * (r0.x + e0.x); r0.y = 0.25f * (r0.y + e0.y);
            r0.z = 0.25f * (r0.z + e0.z); r0.w = 0.25f * (r0.w + e0.w);
            r1.x = 0.25f * (r1.x + e1.x); r1.y = 0.25f * (r1.y + e1.y);
            r1.z = 0.25f * (r1.z + e1.z); r1.w = 0.25f * (r1.w + e1.w);
            out[(size_t)w * 16 + seg * 2]     = r0;
            out[(size_t)w * 16 + seg * 2 + 1] = r1;
        }
    }
}

extern "C" void kernel_launch(void* const* d_in, const int* in_sizes, int n_in,
                              void* d_out, int out_size) {
    const float4* u    = (const float4*)d_in[0];
    const float4* it   = (const float4*)d_in[1];
    const float*  vals = (const float*) d_in[2];
    const int*    rows = (const int*)   d_in[3];
    const int*    cols = (const int*)   d_in[4];
    float4* out = (float4*)d_out;

    k_conv<<<(NV / 4 + 255) / 256, 256>>>(u, it);
    k_scatter<<<(NNZ_E / 2 + 255) / 256, 256>>>(vals, rows, cols);
    k_pad<<<(NN + 255) / 256, 256>>>();

    uint4* h0; uint4* h1; uint4* h2;
    cudaGetSymbolAddress((void**)&h0, g_h0);
    cudaGetSymbolAddress((void**)&h1, g_h1);
    cudaGetSymbolAddress((void**)&h2, g_h2);

    const int spmm_blocks = (NN * 32 + 255) / 256;
    k_spmm<false><<<spmm_blocks, 256>>>(h0, h1, nullptr, nullptr, nullptr); // L1
    k_spmm<false><<<spmm_blocks, 256>>>(h1, h2, nullptr, nullptr, nullptr); // L2
    k_spmm<true ><<<spmm_blocks, 256>>>(h2, nullptr, u, it, out);           // L3+comb
}